// round 8
// baseline (speedup 1.0000x reference)
#include <cuda_runtime.h>
#include <cstdint>

// Problem constants
#define D_MODEL 1024
#define NUM_HEADS 16
#define HEAD_DIM 64
#define BATCH 2
#define SEQ 2048
#define NTOK 4096
#define D3 3072

// ---------------------------------------------------------------------------
// Scratch (no cudaMalloc allowed)
// ---------------------------------------------------------------------------
__device__ float g_qkv[NTOK * D3];                          // rounded Q|K|V
__device__ float g_ctx[NTOK * D_MODEL];                     // rounded ctx
__device__ float g_xr[NTOK * D_MODEL];                      // rounded x
__device__ float g_wqkvr[D_MODEL * D3];                     // rounded Wqkv
__device__ float g_wprojr[D_MODEL * D_MODEL];               // rounded Wproj

// ---------------------------------------------------------------------------
// helpers
// ---------------------------------------------------------------------------
__device__ __forceinline__ uint32_t smem_to_u32(const void* p) {
    uint32_t a;
    asm("{ .reg .u64 t; cvta.to.shared.u64 t, %1; cvt.u32.u64 %0, t; }"
        : "=r"(a) : "l"(p));
    return a;
}
__device__ __forceinline__ uint32_t f2tf(float f) {
    uint32_t u; asm("cvt.rna.tf32.f32 %0, %1;" : "=r"(u) : "f"(f)); return u;
}
__device__ __forceinline__ float f2tf_f(float f) { return __uint_as_float(f2tf(f)); }

__device__ __forceinline__ void mma_tf32(float d[4], const uint32_t a[4],
                                         const uint32_t b[2]) {
    asm volatile(
        "mma.sync.aligned.m16n8k8.row.col.f32.tf32.tf32.f32 "
        "{%0,%1,%2,%3}, {%4,%5,%6,%7}, {%8,%9}, {%0,%1,%2,%3};"
        : "+f"(d[0]), "+f"(d[1]), "+f"(d[2]), "+f"(d[3])
        : "r"(a[0]), "r"(a[1]), "r"(a[2]), "r"(a[3]), "r"(b[0]), "r"(b[1]));
}

#define CP_ASYNC16(dst, src) \
    asm volatile("cp.async.cg.shared.global [%0], [%1], 16;" \
                 :: "r"((uint32_t)(dst)), "l"(src) : "memory")
#define CP_COMMIT asm volatile("cp.async.commit_group;" ::: "memory")
#define CP_WAIT1  asm volatile("cp.async.wait_group 1;" ::: "memory")
#define CP_WAIT0  asm volatile("cp.async.wait_group 0;" ::: "memory")

// ---------------------------------------------------------------------------
// Pre-pass: fp32 -> tf32-rounded fp32 copy
// ---------------------------------------------------------------------------
__global__ __launch_bounds__(256) void round_copy_kernel(
    const float* __restrict__ src, float* __restrict__ dst, int n)
{
    int i = (blockIdx.x * 256 + threadIdx.x) * 4;
    if (i >= n) return;
    float4 v = *(const float4*)(src + i);
    v.x = f2tf_f(v.x); v.y = f2tf_f(v.y);
    v.z = f2tf_f(v.z); v.w = f2tf_f(v.w);
    *(float4*)(dst + i) = v;
}

// ---------------------------------------------------------------------------
// GEMM (tf32 mma, cp.async 3-stage, single sync per iter):
//   C[M,N] = A[M,K] @ W[K,N] + bias[N]   (A, W pre-rounded to tf32)
// 128x128 CTA tile, BK=32, 128 threads = 4 warps of 64x64 tiles (2x2).
// ---------------------------------------------------------------------------
#define BM 128
#define BN 128
#define BK 32
#define AS_STRIDE 36
#define BS_STRIDE 136
#define STAGE_F (BM * AS_STRIDE + BK * BS_STRIDE)   // 8960 floats
#define GEMM_SMEM (3 * STAGE_F * 4)                 // 107520 B

__global__ __launch_bounds__(128, 2) void gemm_tf32_kernel(
    const float* __restrict__ A, const float* __restrict__ W,
    const float* __restrict__ bias, float* __restrict__ C,
    int M, int N, int K, int do_round)
{
    extern __shared__ float sm[];
    const uint32_t smb = smem_to_u32(sm);

    const int tid  = threadIdx.x;
    const int lane = tid & 31;
    const int wid  = tid >> 5;
    const int wm = (wid >> 1) * 64;       // 0 / 64
    const int wn = (wid & 1) * 64;        // 0 / 64
    const int bm = blockIdx.y * BM;
    const int bn = blockIdx.x * BN;
    const int lq = lane >> 2;
    const int lr = lane & 3;

    auto issue_stage = [&](int buf, int kt) {
        const uint32_t base = smb + buf * STAGE_F * 4;
#pragma unroll
        for (int i = 0; i < 8; i++) {
            int f = tid + i * 128;
            int row = f >> 3, c4 = (f & 7) * 4;
            CP_ASYNC16(base + (row * AS_STRIDE + c4) * 4,
                       A + (size_t)(bm + row) * K + kt + c4);
        }
#pragma unroll
        for (int i = 0; i < 8; i++) {
            int f = tid + i * 128;
            int row = f >> 5, c4 = (f & 31) * 4;
            CP_ASYNC16(base + (BM * AS_STRIDE + row * BS_STRIDE + c4) * 4,
                       W + (size_t)(kt + row) * N + bn + c4);
        }
    };

    float acc[4][8][4];
#pragma unroll
    for (int i = 0; i < 4; i++)
#pragma unroll
        for (int j = 0; j < 8; j++)
#pragma unroll
            for (int e = 0; e < 4; e++) acc[i][j][e] = 0.0f;

    const int NT = K / BK;                // 32
    issue_stage(0, 0);
    CP_COMMIT;
    issue_stage(1, BK);
    CP_COMMIT;

    for (int t = 0; t < NT; t++) {
        const int buf = t % 3;
        if (t < NT - 1) { CP_WAIT1; } else { CP_WAIT0; }
        __syncthreads();                  // single sync per iteration
        if (t + 2 < NT) {
            issue_stage((t + 2) % 3, (t + 2) * BK);
            CP_COMMIT;
        }

        const float* As = sm + buf * STAGE_F;
        const float* Bs = As + BM * AS_STRIDE;
#pragma unroll
        for (int ks = 0; ks < 4; ks++) {
            uint32_t af[4][4];
#pragma unroll
            for (int i = 0; i < 4; i++) {
                const float* p = &As[(wm + i * 16 + lq) * AS_STRIDE + ks * 8 + lr];
                af[i][0] = __float_as_uint(p[0]);
                af[i][1] = __float_as_uint(p[8 * AS_STRIDE]);
                af[i][2] = __float_as_uint(p[4]);
                af[i][3] = __float_as_uint(p[8 * AS_STRIDE + 4]);
            }
#pragma unroll
            for (int j = 0; j < 8; j++) {
                uint32_t bf[2];
                const float* p = &Bs[(ks * 8 + lr) * BS_STRIDE + wn + j * 8 + lq];
                bf[0] = __float_as_uint(p[0]);
                bf[1] = __float_as_uint(p[4 * BS_STRIDE]);
                mma_tf32(acc[0][j], af[0], bf);
                mma_tf32(acc[1][j], af[1], bf);
                mma_tf32(acc[2][j], af[2], bf);
                mma_tf32(acc[3][j], af[3], bf);
            }
        }
    }

    // epilogue: bias (+ optional tf32 rounding) + store
#pragma unroll
    for (int i = 0; i < 4; i++) {
        const int r0 = bm + wm + i * 16 + lq;
#pragma unroll
        for (int j = 0; j < 8; j++) {
            const int col = bn + wn + j * 8 + lr * 2;
            const float b0 = bias[col], b1 = bias[col + 1];
            float v0 = acc[i][j][0] + b0, v1 = acc[i][j][1] + b1;
            float v2 = acc[i][j][2] + b0, v3 = acc[i][j][3] + b1;
            if (do_round) {
                v0 = f2tf_f(v0); v1 = f2tf_f(v1);
                v2 = f2tf_f(v2); v3 = f2tf_f(v3);
            }
            *(float2*)&C[(size_t)r0 * N + col] = make_float2(v0, v1);
            *(float2*)&C[(size_t)(r0 + 8) * N + col] = make_float2(v2, v3);
        }
    }
}

// ---------------------------------------------------------------------------
// Attention: 256 queries/CTA, 16 warps (512 threads), 64-key tiles,
// cp.async 3-stage, single sync per tile. V staged in natural [key][hd]
// layout (stride 72). Softmax in log2 domain, scale folded into Q.
// K/V traffic halved vs 128q/CTA. grid (SEQ/256, H, B), block 512.
// ---------------------------------------------------------------------------
#define KTS 68                        // K tile stride (68 mod 32 == 4)
#define VTS 72                        // V tile stride (72 mod 32 == 8)
#define KT_FK (64 * KTS)              // 4352
#define KT_FV (64 * VTS)              // 4608
#define OFF_V (3 * KT_FK)
#define OFF_M (3 * KT_FK + 3 * KT_FV)
#define ATT_SMEM ((3 * KT_FK + 3 * KT_FV + 3 * 64) * 4)  // 108288 B
#define NKT (SEQ / 64)

#define SCALE_LOG2E 0.18033688011112042f   // 0.125 * log2(e)

__global__ __launch_bounds__(512, 1) void attn2_kernel(const int* __restrict__ mask)
{
    extern __shared__ float sm[];
    const uint32_t smb = smem_to_u32(sm);
    const int tid = threadIdx.x, lane = tid & 31, w = tid >> 5;   // w: 0..15
    const int lq = lane >> 2, lr = lane & 3;
    const int h = blockIdx.y, b = blockIdx.z;
    const int q0 = blockIdx.x * 256;
    const size_t tokbase = (size_t)b * SEQ;

    const float* Kg = g_qkv + tokbase * D3 + D_MODEL + h * HEAD_DIM;
    const float* VgG = g_qkv + tokbase * D3 + 2 * D_MODEL + h * HEAD_DIM;
    const int* mg = mask + b * SEQ;

    auto issue_stage = [&](int buf, int kt) {
#pragma unroll
        for (int i = 0; i < 2; i++) {
            int f = tid + i * 512;
            int row = f >> 4, c4 = (f & 15) * 4;
            CP_ASYNC16(smb + (buf * KT_FK + row * KTS + c4) * 4,
                       Kg + (size_t)(kt + row) * D3 + c4);
            CP_ASYNC16(smb + (OFF_V + buf * KT_FV + row * VTS + c4) * 4,
                       VgG + (size_t)(kt + row) * D3 + c4);
        }
        if (tid < 16)
            CP_ASYNC16(smb + (OFF_M + buf * 64) * 4 + tid * 16,
                       mg + kt + tid * 4);
    };
    issue_stage(0, 0);
    CP_COMMIT;
    issue_stage(1, 64);
    CP_COMMIT;

    // Q fragments from GMEM, pre-scaled by 0.125*log2e, re-rounded to tf32
    uint32_t qa[8][4];
    {
        const float* Qb = g_qkv + (tokbase + q0 + w * 16 + lq) * D3 + h * HEAD_DIM;
#pragma unroll
        for (int ks = 0; ks < 8; ks++) {
            qa[ks][0] = f2tf(Qb[ks * 8 + lr] * SCALE_LOG2E);
            qa[ks][1] = f2tf(Qb[8 * D3 + ks * 8 + lr] * SCALE_LOG2E);
            qa[ks][2] = f2tf(Qb[ks * 8 + lr + 4] * SCALE_LOG2E);
            qa[ks][3] = f2tf(Qb[8 * D3 + ks * 8 + lr + 4] * SCALE_LOG2E);
        }
    }

    float O[8][4];
#pragma unroll
    for (int j = 0; j < 8; j++)
#pragma unroll
        for (int e = 0; e < 4; e++) O[j][e] = 0.0f;
    float m0 = -1e30f, m1 = -1e30f, l0 = 0.0f, l1 = 0.0f;

    for (int t = 0; t < NKT; t++) {
        const int s = t % 3;
        if (t < NKT - 1) { CP_WAIT1; } else { CP_WAIT0; }
        __syncthreads();                  // single sync per tile
        if (t + 2 < NKT) {
            issue_stage((t + 2) % 3, (t + 2) * 64);
            CP_COMMIT;
        }

        const float* Ksb = sm + s * KT_FK;
        const float* Vsb = sm + OFF_V + s * KT_FV;
        const int* mib = (const int*)(sm + OFF_M + s * 64);

        // S (log2-scaled) = (c*Q) @ K^T
        float sv[8][4];
#pragma unroll
        for (int j = 0; j < 8; j++)
#pragma unroll
            for (int e = 0; e < 4; e++) sv[j][e] = 0.0f;
#pragma unroll
        for (int ks = 0; ks < 8; ks++) {
#pragma unroll
            for (int j = 0; j < 8; j++) {
                uint32_t bf[2];
                const float* p = &Ksb[(j * 8 + lq) * KTS + ks * 8 + lr];
                bf[0] = __float_as_uint(p[0]);
                bf[1] = __float_as_uint(p[4]);
                mma_tf32(sv[j], qa[ks], bf);
            }
        }

        // mask + online softmax (base-2)
        float mx0 = -1e30f, mx1 = -1e30f;
#pragma unroll
        for (int j = 0; j < 8; j++) {
            const float bias0 = mib[j * 8 + lr * 2] ? 0.0f : -1e30f;
            const float bias1 = mib[j * 8 + lr * 2 + 1] ? 0.0f : -1e30f;
            sv[j][0] += bias0;
            sv[j][1] += bias1;
            sv[j][2] += bias0;
            sv[j][3] += bias1;
            mx0 = fmaxf(mx0, fmaxf(sv[j][0], sv[j][1]));
            mx1 = fmaxf(mx1, fmaxf(sv[j][2], sv[j][3]));
        }
        mx0 = fmaxf(mx0, __shfl_xor_sync(0xffffffffu, mx0, 1));
        mx0 = fmaxf(mx0, __shfl_xor_sync(0xffffffffu, mx0, 2));
        mx1 = fmaxf(mx1, __shfl_xor_sync(0xffffffffu, mx1, 1));
        mx1 = fmaxf(mx1, __shfl_xor_sync(0xffffffffu, mx1, 2));

        const float mn0 = fmaxf(m0, mx0), mn1 = fmaxf(m1, mx1);
        const float c0 = exp2f(m0 - mn0), c1 = exp2f(m1 - mn1);
        float sum0 = 0.0f, sum1 = 0.0f;
#pragma unroll
        for (int j = 0; j < 8; j++) {
            float e0 = exp2f(sv[j][0] - mn0);
            float e1 = exp2f(sv[j][1] - mn0);
            float e2 = exp2f(sv[j][2] - mn1);
            float e3 = exp2f(sv[j][3] - mn1);
            sum0 += e0 + e1;
            sum1 += e2 + e3;
            sv[j][0] = f2tf_f(e0);
            sv[j][1] = f2tf_f(e1);
            sv[j][2] = f2tf_f(e2);
            sv[j][3] = f2tf_f(e3);
        }
        sum0 += __shfl_xor_sync(0xffffffffu, sum0, 1);
        sum0 += __shfl_xor_sync(0xffffffffu, sum0, 2);
        sum1 += __shfl_xor_sync(0xffffffffu, sum1, 1);
        sum1 += __shfl_xor_sync(0xffffffffu, sum1, 2);
        l0 = l0 * c0 + sum0;
        l1 = l1 * c1 + sum1;
        m0 = mn0; m1 = mn1;
#pragma unroll
        for (int j = 0; j < 8; j++) {
            O[j][0] *= c0; O[j][1] *= c0;
            O[j][2] *= c1; O[j][3] *= c1;
        }

        // O += P @ V ; P C-frag -> A-frag via quad shuffles; V read [key][hd]
        const int srcA = (lane & ~3) | (lr >> 1);
        const int srcB = srcA + 2;
        const bool odd = (lr & 1);
#pragma unroll
        for (int ks = 0; ks < 8; ks++) {
            uint32_t pa[4];
            {
                float a0 = __shfl_sync(0xffffffffu, sv[ks][0], srcA);
                float a1 = __shfl_sync(0xffffffffu, sv[ks][1], srcA);
                float a2 = __shfl_sync(0xffffffffu, sv[ks][2], srcA);
                float a3 = __shfl_sync(0xffffffffu, sv[ks][3], srcA);
                float b0 = __shfl_sync(0xffffffffu, sv[ks][0], srcB);
                float b1 = __shfl_sync(0xffffffffu, sv[ks][1], srcB);
                float b2 = __shfl_sync(0xffffffffu, sv[ks][2], srcB);
                float b3 = __shfl_sync(0xffffffffu, sv[ks][3], srcB);
                pa[0] = __float_as_uint(odd ? a1 : a0);
                pa[1] = __float_as_uint(odd ? a3 : a2);
                pa[2] = __float_as_uint(odd ? b1 : b0);
                pa[3] = __float_as_uint(odd ? b3 : b2);
            }
#pragma unroll
            for (int j = 0; j < 8; j++) {
                uint32_t bf[2];
                bf[0] = __float_as_uint(Vsb[(ks * 8 + lr) * VTS + j * 8 + lq]);
                bf[1] = __float_as_uint(Vsb[(ks * 8 + lr + 4) * VTS + j * 8 + lq]);
                mma_tf32(O[j], pa, bf);
            }
        }
    }

    // normalize + store ctx (tf32-rounded for proj A operand)
    const float inv0 = 1.0f / l0, inv1 = 1.0f / l1;
    const int r0 = q0 + w * 16 + lq;
#pragma unroll
    for (int j = 0; j < 8; j++) {
        const int col = h * HEAD_DIM + j * 8 + lr * 2;
        float2 o0 = make_float2(f2tf_f(O[j][0] * inv0), f2tf_f(O[j][1] * inv0));
        float2 o1 = make_float2(f2tf_f(O[j][2] * inv1), f2tf_f(O[j][3] * inv1));
        *(float2*)&g_ctx[(tokbase + r0) * D_MODEL + col] = o0;
        *(float2*)&g_ctx[(tokbase + r0 + 8) * D_MODEL + col] = o1;
    }
}

// ---------------------------------------------------------------------------
// Launch
// ---------------------------------------------------------------------------
extern "C" void kernel_launch(void* const* d_in, const int* in_sizes, int n_in,
                              void* d_out, int out_size)
{
    const float* x     = (const float*)d_in[0];
    const int*   mask  = (const int*)d_in[1];
    const float* Wqkv  = (const float*)d_in[2];
    const float* bqkv  = (const float*)d_in[3];
    const float* Wproj = (const float*)d_in[4];
    const float* bproj = (const float*)d_in[5];
    float* out = (float*)d_out;

    float *qkv, *ctx, *xr, *wqkvr, *wprojr;
    cudaGetSymbolAddress((void**)&qkv,    g_qkv);
    cudaGetSymbolAddress((void**)&ctx,    g_ctx);
    cudaGetSymbolAddress((void**)&xr,     g_xr);
    cudaGetSymbolAddress((void**)&wqkvr,  g_wqkvr);
    cudaGetSymbolAddress((void**)&wprojr, g_wprojr);

    cudaFuncSetAttribute(gemm_tf32_kernel,
                         cudaFuncAttributeMaxDynamicSharedMemorySize, GEMM_SMEM);
    cudaFuncSetAttribute(attn2_kernel,
                         cudaFuncAttributeMaxDynamicSharedMemorySize, ATT_SMEM);

    // 0) round inputs to tf32 once
    round_copy_kernel<<<NTOK * D_MODEL / 1024, 256>>>(x, xr, NTOK * D_MODEL);
    round_copy_kernel<<<D_MODEL * D3 / 1024, 256>>>(Wqkv, wqkvr, D_MODEL * D3);
    round_copy_kernel<<<D_MODEL * D_MODEL / 1024, 256>>>(Wproj, wprojr,
                                                         D_MODEL * D_MODEL);

    // 1) QKV GEMM -> g_qkv (rounded outputs)
    {
        dim3 grid(D3 / BN, NTOK / BM);
        gemm_tf32_kernel<<<grid, 128, GEMM_SMEM>>>(
            xr, wqkvr, bqkv, qkv, NTOK, D3, D_MODEL, 1);
    }
    // 2) Attention -> g_ctx (rounded)
    {
        dim3 grid(SEQ / 256, NUM_HEADS, BATCH);
        attn2_kernel<<<grid, 512, ATT_SMEM>>>(mask);
    }
    // 3) Output projection -> out (no rounding)
    {
        dim3 grid(D_MODEL / BN, NTOK / BM);
        gemm_tf32_kernel<<<grid, 128, GEMM_SMEM>>>(
            ctx, wprojr, bproj, out, NTOK, D_MODEL, D_MODEL, 0);
    }
}

// round 9
// speedup vs baseline: 1.0715x; 1.0715x over previous
#include <cuda_runtime.h>
#include <cstdint>

// Problem constants
#define D_MODEL 1024
#define NUM_HEADS 16
#define HEAD_DIM 64
#define BATCH 2
#define SEQ 2048
#define NTOK 4096
#define D3 3072

// ---------------------------------------------------------------------------
// Scratch (no cudaMalloc allowed)
// ---------------------------------------------------------------------------
__device__ float g_qkv[NTOK * D3];                          // rounded Q|K|V
__device__ float g_ctx[NTOK * D_MODEL];                     // rounded ctx

// ---------------------------------------------------------------------------
// helpers
// ---------------------------------------------------------------------------
__device__ __forceinline__ uint32_t smem_to_u32(const void* p) {
    uint32_t a;
    asm("{ .reg .u64 t; cvta.to.shared.u64 t, %1; cvt.u32.u64 %0, t; }"
        : "=r"(a) : "l"(p));
    return a;
}
__device__ __forceinline__ uint32_t f2tf(float f) {
    uint32_t u; asm("cvt.rna.tf32.f32 %0, %1;" : "=r"(u) : "f"(f)); return u;
}
__device__ __forceinline__ float f2tf_f(float f) { return __uint_as_float(f2tf(f)); }

__device__ __forceinline__ void mma_tf32(float d[4], const uint32_t a[4],
                                         const uint32_t b[2]) {
    asm volatile(
        "mma.sync.aligned.m16n8k8.row.col.f32.tf32.tf32.f32 "
        "{%0,%1,%2,%3}, {%4,%5,%6,%7}, {%8,%9}, {%0,%1,%2,%3};"
        : "+f"(d[0]), "+f"(d[1]), "+f"(d[2]), "+f"(d[3])
        : "r"(a[0]), "r"(a[1]), "r"(a[2]), "r"(a[3]), "r"(b[0]), "r"(b[1]));
}

#define CP_ASYNC16(dst, src) \
    asm volatile("cp.async.cg.shared.global [%0], [%1], 16;" \
                 :: "r"((uint32_t)(dst)), "l"(src) : "memory")
#define CP_COMMIT asm volatile("cp.async.commit_group;" ::: "memory")
#define CP_WAIT1  asm volatile("cp.async.wait_group 1;" ::: "memory")
#define CP_WAIT0  asm volatile("cp.async.wait_group 0;" ::: "memory")

// ---------------------------------------------------------------------------
// GEMM (tf32 mma, cp.async 3-stage, single sync per iter):
//   C[M,N] = A[M,K] @ W[K,N] + bias[N]
// Inputs are raw fp32; the tf32 mma datapath truncates operands to tf32.
// 128x128 CTA tile, BK=32, 128 threads = 4 warps of 64x64 tiles (2x2).
// ---------------------------------------------------------------------------
#define BM 128
#define BN 128
#define BK 32
#define AS_STRIDE 36
#define BS_STRIDE 136
#define STAGE_F (BM * AS_STRIDE + BK * BS_STRIDE)   // 8960 floats
#define GEMM_SMEM (3 * STAGE_F * 4)                 // 107520 B

__global__ __launch_bounds__(128, 2) void gemm_tf32_kernel(
    const float* __restrict__ A, const float* __restrict__ W,
    const float* __restrict__ bias, float* __restrict__ C,
    int M, int N, int K, int do_round)
{
    extern __shared__ float sm[];
    const uint32_t smb = smem_to_u32(sm);

    const int tid  = threadIdx.x;
    const int lane = tid & 31;
    const int wid  = tid >> 5;
    const int wm = (wid >> 1) * 64;       // 0 / 64
    const int wn = (wid & 1) * 64;        // 0 / 64
    const int bm = blockIdx.y * BM;
    const int bn = blockIdx.x * BN;
    const int lq = lane >> 2;
    const int lr = lane & 3;

    auto issue_stage = [&](int buf, int kt) {
        const uint32_t base = smb + buf * STAGE_F * 4;
#pragma unroll
        for (int i = 0; i < 8; i++) {
            int f = tid + i * 128;
            int row = f >> 3, c4 = (f & 7) * 4;
            CP_ASYNC16(base + (row * AS_STRIDE + c4) * 4,
                       A + (size_t)(bm + row) * K + kt + c4);
        }
#pragma unroll
        for (int i = 0; i < 8; i++) {
            int f = tid + i * 128;
            int row = f >> 5, c4 = (f & 31) * 4;
            CP_ASYNC16(base + (BM * AS_STRIDE + row * BS_STRIDE + c4) * 4,
                       W + (size_t)(kt + row) * N + bn + c4);
        }
    };

    float acc[4][8][4];
#pragma unroll
    for (int i = 0; i < 4; i++)
#pragma unroll
        for (int j = 0; j < 8; j++)
#pragma unroll
            for (int e = 0; e < 4; e++) acc[i][j][e] = 0.0f;

    const int NT = K / BK;                // 32
    issue_stage(0, 0);
    CP_COMMIT;
    issue_stage(1, BK);
    CP_COMMIT;

    for (int t = 0; t < NT; t++) {
        const int buf = t % 3;
        if (t < NT - 1) { CP_WAIT1; } else { CP_WAIT0; }
        __syncthreads();                  // single sync per iteration
        if (t + 2 < NT) {
            issue_stage((t + 2) % 3, (t + 2) * BK);
            CP_COMMIT;
        }

        const float* As = sm + buf * STAGE_F;
        const float* Bs = As + BM * AS_STRIDE;
#pragma unroll
        for (int ks = 0; ks < 4; ks++) {
            uint32_t af[4][4];
#pragma unroll
            for (int i = 0; i < 4; i++) {
                const float* p = &As[(wm + i * 16 + lq) * AS_STRIDE + ks * 8 + lr];
                af[i][0] = __float_as_uint(p[0]);
                af[i][1] = __float_as_uint(p[8 * AS_STRIDE]);
                af[i][2] = __float_as_uint(p[4]);
                af[i][3] = __float_as_uint(p[8 * AS_STRIDE + 4]);
            }
#pragma unroll
            for (int j = 0; j < 8; j++) {
                uint32_t bf[2];
                const float* p = &Bs[(ks * 8 + lr) * BS_STRIDE + wn + j * 8 + lq];
                bf[0] = __float_as_uint(p[0]);
                bf[1] = __float_as_uint(p[4 * BS_STRIDE]);
                mma_tf32(acc[0][j], af[0], bf);
                mma_tf32(acc[1][j], af[1], bf);
                mma_tf32(acc[2][j], af[2], bf);
                mma_tf32(acc[3][j], af[3], bf);
            }
        }
    }

    // epilogue: bias (+ optional tf32 rounding) + store
#pragma unroll
    for (int i = 0; i < 4; i++) {
        const int r0 = bm + wm + i * 16 + lq;
#pragma unroll
        for (int j = 0; j < 8; j++) {
            const int col = bn + wn + j * 8 + lr * 2;
            const float b0 = bias[col], b1 = bias[col + 1];
            float v0 = acc[i][j][0] + b0, v1 = acc[i][j][1] + b1;
            float v2 = acc[i][j][2] + b0, v3 = acc[i][j][3] + b1;
            if (do_round) {
                v0 = f2tf_f(v0); v1 = f2tf_f(v1);
                v2 = f2tf_f(v2); v3 = f2tf_f(v3);
            }
            *(float2*)&C[(size_t)r0 * N + col] = make_float2(v0, v1);
            *(float2*)&C[(size_t)(r0 + 8) * N + col] = make_float2(v2, v3);
        }
    }
}

// ---------------------------------------------------------------------------
// Attention: 128 queries/CTA, 8 warps, 64-key tiles, cp.async 3-stage,
// single sync per tile. V staged in natural [key][hd] layout (stride 72).
// Softmax in log2 domain, scale folded into Q fragments.
// grid (SEQ/128, H, B), block 256.
// ---------------------------------------------------------------------------
#define KTS 68                        // K tile stride (68 mod 32 == 4)
#define VTS 72                        // V tile stride (72 mod 32 == 8)
#define KT_FK (64 * KTS)              // 4352
#define KT_FV (64 * VTS)              // 4608
#define OFF_V (3 * KT_FK)
#define OFF_M (3 * KT_FK + 3 * KT_FV)
#define ATT_SMEM ((3 * KT_FK + 3 * KT_FV + 3 * 64) * 4)  // 108288 B
#define NKT (SEQ / 64)

#define SCALE_LOG2E 0.18033688011112042f   // 0.125 * log2(e)

__global__ __launch_bounds__(256, 2) void attn2_kernel(const int* __restrict__ mask)
{
    extern __shared__ float sm[];
    const uint32_t smb = smem_to_u32(sm);
    const int tid = threadIdx.x, lane = tid & 31, w = tid >> 5;
    const int lq = lane >> 2, lr = lane & 3;
    const int h = blockIdx.y, b = blockIdx.z;
    const int q0 = blockIdx.x * 128;
    const size_t tokbase = (size_t)b * SEQ;

    const float* Kg = g_qkv + tokbase * D3 + D_MODEL + h * HEAD_DIM;
    const float* VgG = g_qkv + tokbase * D3 + 2 * D_MODEL + h * HEAD_DIM;
    const int* mg = mask + b * SEQ;

    auto issue_stage = [&](int buf, int kt) {
#pragma unroll
        for (int i = 0; i < 4; i++) {
            int f = tid + i * 256;
            int row = f >> 4, c4 = (f & 15) * 4;
            CP_ASYNC16(smb + (buf * KT_FK + row * KTS + c4) * 4,
                       Kg + (size_t)(kt + row) * D3 + c4);
            CP_ASYNC16(smb + (OFF_V + buf * KT_FV + row * VTS + c4) * 4,
                       VgG + (size_t)(kt + row) * D3 + c4);
        }
        if (tid < 16)
            CP_ASYNC16(smb + (OFF_M + buf * 64) * 4 + tid * 16,
                       mg + kt + tid * 4);
    };
    issue_stage(0, 0);
    CP_COMMIT;
    issue_stage(1, 64);
    CP_COMMIT;

    // Q fragments from GMEM, pre-scaled by 0.125*log2e, re-rounded to tf32
    uint32_t qa[8][4];
    {
        const float* Qb = g_qkv + (tokbase + q0 + w * 16 + lq) * D3 + h * HEAD_DIM;
#pragma unroll
        for (int ks = 0; ks < 8; ks++) {
            qa[ks][0] = f2tf(Qb[ks * 8 + lr] * SCALE_LOG2E);
            qa[ks][1] = f2tf(Qb[8 * D3 + ks * 8 + lr] * SCALE_LOG2E);
            qa[ks][2] = f2tf(Qb[ks * 8 + lr + 4] * SCALE_LOG2E);
            qa[ks][3] = f2tf(Qb[8 * D3 + ks * 8 + lr + 4] * SCALE_LOG2E);
        }
    }

    float O[8][4];
#pragma unroll
    for (int j = 0; j < 8; j++)
#pragma unroll
        for (int e = 0; e < 4; e++) O[j][e] = 0.0f;
    float m0 = -1e30f, m1 = -1e30f, l0 = 0.0f, l1 = 0.0f;

    for (int t = 0; t < NKT; t++) {
        const int s = t % 3;
        if (t < NKT - 1) { CP_WAIT1; } else { CP_WAIT0; }
        __syncthreads();                  // single sync per tile
        if (t + 2 < NKT) {
            issue_stage((t + 2) % 3, (t + 2) * 64);
            CP_COMMIT;
        }

        const float* Ksb = sm + s * KT_FK;
        const float* Vsb = sm + OFF_V + s * KT_FV;
        const int* mib = (const int*)(sm + OFF_M + s * 64);

        // S (log2-scaled) = (c*Q) @ K^T
        float sv[8][4];
#pragma unroll
        for (int j = 0; j < 8; j++)
#pragma unroll
            for (int e = 0; e < 4; e++) sv[j][e] = 0.0f;
#pragma unroll
        for (int ks = 0; ks < 8; ks++) {
#pragma unroll
            for (int j = 0; j < 8; j++) {
                uint32_t bf[2];
                const float* p = &Ksb[(j * 8 + lq) * KTS + ks * 8 + lr];
                bf[0] = __float_as_uint(p[0]);
                bf[1] = __float_as_uint(p[4]);
                mma_tf32(sv[j], qa[ks], bf);
            }
        }

        // mask + online softmax (base-2)
        float mx0 = -1e30f, mx1 = -1e30f;
#pragma unroll
        for (int j = 0; j < 8; j++) {
            const float bias0 = mib[j * 8 + lr * 2] ? 0.0f : -1e30f;
            const float bias1 = mib[j * 8 + lr * 2 + 1] ? 0.0f : -1e30f;
            sv[j][0] += bias0;
            sv[j][1] += bias1;
            sv[j][2] += bias0;
            sv[j][3] += bias1;
            mx0 = fmaxf(mx0, fmaxf(sv[j][0], sv[j][1]));
            mx1 = fmaxf(mx1, fmaxf(sv[j][2], sv[j][3]));
        }
        mx0 = fmaxf(mx0, __shfl_xor_sync(0xffffffffu, mx0, 1));
        mx0 = fmaxf(mx0, __shfl_xor_sync(0xffffffffu, mx0, 2));
        mx1 = fmaxf(mx1, __shfl_xor_sync(0xffffffffu, mx1, 1));
        mx1 = fmaxf(mx1, __shfl_xor_sync(0xffffffffu, mx1, 2));

        const float mn0 = fmaxf(m0, mx0), mn1 = fmaxf(m1, mx1);
        const float c0 = exp2f(m0 - mn0), c1 = exp2f(m1 - mn1);
        float sum0 = 0.0f, sum1 = 0.0f;
#pragma unroll
        for (int j = 0; j < 8; j++) {
            float e0 = exp2f(sv[j][0] - mn0);
            float e1 = exp2f(sv[j][1] - mn0);
            float e2 = exp2f(sv[j][2] - mn1);
            float e3 = exp2f(sv[j][3] - mn1);
            sum0 += e0 + e1;
            sum1 += e2 + e3;
            sv[j][0] = f2tf_f(e0);
            sv[j][1] = f2tf_f(e1);
            sv[j][2] = f2tf_f(e2);
            sv[j][3] = f2tf_f(e3);
        }
        sum0 += __shfl_xor_sync(0xffffffffu, sum0, 1);
        sum0 += __shfl_xor_sync(0xffffffffu, sum0, 2);
        sum1 += __shfl_xor_sync(0xffffffffu, sum1, 1);
        sum1 += __shfl_xor_sync(0xffffffffu, sum1, 2);
        l0 = l0 * c0 + sum0;
        l1 = l1 * c1 + sum1;
        m0 = mn0; m1 = mn1;
#pragma unroll
        for (int j = 0; j < 8; j++) {
            O[j][0] *= c0; O[j][1] *= c0;
            O[j][2] *= c1; O[j][3] *= c1;
        }

        // O += P @ V ; P C-frag -> A-frag via quad shuffles; V read [key][hd]
        const int srcA = (lane & ~3) | (lr >> 1);
        const int srcB = srcA + 2;
        const bool odd = (lr & 1);
#pragma unroll
        for (int ks = 0; ks < 8; ks++) {
            uint32_t pa[4];
            {
                float a0 = __shfl_sync(0xffffffffu, sv[ks][0], srcA);
                float a1 = __shfl_sync(0xffffffffu, sv[ks][1], srcA);
                float a2 = __shfl_sync(0xffffffffu, sv[ks][2], srcA);
                float a3 = __shfl_sync(0xffffffffu, sv[ks][3], srcA);
                float b0 = __shfl_sync(0xffffffffu, sv[ks][0], srcB);
                float b1 = __shfl_sync(0xffffffffu, sv[ks][1], srcB);
                float b2 = __shfl_sync(0xffffffffu, sv[ks][2], srcB);
                float b3 = __shfl_sync(0xffffffffu, sv[ks][3], srcB);
                pa[0] = __float_as_uint(odd ? a1 : a0);
                pa[1] = __float_as_uint(odd ? a3 : a2);
                pa[2] = __float_as_uint(odd ? b1 : b0);
                pa[3] = __float_as_uint(odd ? b3 : b2);
            }
#pragma unroll
            for (int j = 0; j < 8; j++) {
                uint32_t bf[2];
                bf[0] = __float_as_uint(Vsb[(ks * 8 + lr) * VTS + j * 8 + lq]);
                bf[1] = __float_as_uint(Vsb[(ks * 8 + lr + 4) * VTS + j * 8 + lq]);
                mma_tf32(O[j], pa, bf);
            }
        }
    }

    // normalize + store ctx (tf32-rounded for proj A operand)
    const float inv0 = 1.0f / l0, inv1 = 1.0f / l1;
    const int r0 = q0 + w * 16 + lq;
#pragma unroll
    for (int j = 0; j < 8; j++) {
        const int col = h * HEAD_DIM + j * 8 + lr * 2;
        float2 o0 = make_float2(f2tf_f(O[j][0] * inv0), f2tf_f(O[j][1] * inv0));
        float2 o1 = make_float2(f2tf_f(O[j][2] * inv1), f2tf_f(O[j][3] * inv1));
        *(float2*)&g_ctx[(tokbase + r0) * D_MODEL + col] = o0;
        *(float2*)&g_ctx[(tokbase + r0 + 8) * D_MODEL + col] = o1;
    }
}

// ---------------------------------------------------------------------------
// Launch
// ---------------------------------------------------------------------------
extern "C" void kernel_launch(void* const* d_in, const int* in_sizes, int n_in,
                              void* d_out, int out_size)
{
    const float* x     = (const float*)d_in[0];
    const int*   mask  = (const int*)d_in[1];
    const float* Wqkv  = (const float*)d_in[2];
    const float* bqkv  = (const float*)d_in[3];
    const float* Wproj = (const float*)d_in[4];
    const float* bproj = (const float*)d_in[5];
    float* out = (float*)d_out;

    float *qkv, *ctx;
    cudaGetSymbolAddress((void**)&qkv, g_qkv);
    cudaGetSymbolAddress((void**)&ctx, g_ctx);

    cudaFuncSetAttribute(gemm_tf32_kernel,
                         cudaFuncAttributeMaxDynamicSharedMemorySize, GEMM_SMEM);
    cudaFuncSetAttribute(attn2_kernel,
                         cudaFuncAttributeMaxDynamicSharedMemorySize, ATT_SMEM);

    // 1) QKV GEMM -> g_qkv (rounded outputs); raw fp32 inputs (HW tf32 trunc)
    {
        dim3 grid(D3 / BN, NTOK / BM);
        gemm_tf32_kernel<<<grid, 128, GEMM_SMEM>>>(
            x, Wqkv, bqkv, qkv, NTOK, D3, D_MODEL, 1);
    }
    // 2) Attention -> g_ctx (rounded)
    {
        dim3 grid(SEQ / 128, NUM_HEADS, BATCH);
        attn2_kernel<<<grid, 256, ATT_SMEM>>>(mask);
    }
    // 3) Output projection -> out (no rounding)
    {
        dim3 grid(D_MODEL / BN, NTOK / BM);
        gemm_tf32_kernel<<<grid, 128, GEMM_SMEM>>>(
            ctx, Wproj, bproj, out, NTOK, D_MODEL, D_MODEL, 0);
    }
}